// round 12
// baseline (speedup 1.0000x reference)
#include <cuda_runtime.h>

#define LSEQ     2048
#define NBATCH   32
#define TOTPAIRS (NBATCH * 1024)   // 32768 global pair indices
#define TPB      256
#define NBLOCKS  296               // 2 * 148: two perfectly balanced waves
#define DTC      0.01f

// log2(e)/sqrt(3): fold softmax scale + e^x->2^x conversion into q
#define QSCALE (1.4426950408889634f / 1.7320508075688772f)

__device__ __forceinline__ float ex2(float x) {
    float r;
    asm("ex2.approx.f32 %0, %1;" : "=f"(r) : "f"(x));
    return r;
}

#define PACK2(d, lo, hi)   asm("mov.b64 %0, {%1, %2};" : "=l"(d) : "f"(lo), "f"(hi))
#define UNPACK2(lo, hi, d) asm("mov.b64 {%0, %1}, %2;" : "=f"(lo), "=f"(hi) : "l"(d))
#define FMA2(d, a, b, c)   asm("fma.rn.f32x2 %0, %1, %2, %3;" : "=l"(d) : "l"(a), "l"(b), "l"(c))

__global__ void __launch_bounds__(TPB, 2) ac_kernel(
    const float* __restrict__ inputs,
    const float* __restrict__ wi,  const float* __restrict__ bi,
    const float* __restrict__ wo,  const float* __restrict__ bo,
    const float* __restrict__ f1w, const float* __restrict__ f1b,
    const float* __restrict__ f2w, const float* __restrict__ f2b,
    const float* __restrict__ g1w, const float* __restrict__ g1b,
    const float* __restrict__ g2w, const float* __restrict__ g2b,
    const float* __restrict__ m1s, const float* __restrict__ m2s,
    const float* __restrict__ sigma,
    float* __restrict__ out)
{
    extern __shared__ float4 kv[];   // [2*LSEQ]: kv[2j]={k0,k1,k2,0}, kv[2j+1]={v0,v1,v2,1}

    const int bid = blockIdx.x;
    const int t = threadIdx.x;
    const int u = t & 127;           // slot within half
    const bool hi_half = (t >= 128);

    const float scl0 = sigma[0] + 1e-5f;
    const float scl1 = sigma[1] + 1e-5f;
    const float inv0 = 1.0f / scl0;
    const float inv1 = 1.0f / scl1;

    // epilogue / projection params (L1-hot after wave 1)
    float wo10 = wo[3], wo11 = wo[4], wo12 = wo[5];
    float wo20 = wo[6], wo21 = wo[7], wo22 = wo[8];
    float bo1 = bo[1], bo2 = bo[2];
    float G10 = g1w[0], G11 = g1w[1], G12 = g1w[2], G1B = g1b[0];
    float G20 = g2w[0], G21 = g2w[1], G22 = g2w[2], G2B = g2b[0];
    float F10 = f1w[0], F11 = f1w[1], F12 = f1w[2], F1B = f1b[0];
    float F20 = f2w[0], F21 = f2w[1], F22 = f2w[2], F2B = f2b[0];
    float M1 = m1s[0], M2 = m2s[0];

    // global pair span for this block: equal 110-111 pair spans
    unsigned gp0 = (unsigned)(((unsigned long long)TOTPAIRS * bid) / NBLOCKS);
    unsigned gp1 = (unsigned)(((unsigned long long)TOTPAIRS * (bid + 1)) / NBLOCKS);

    int prev_batch = -1;

    while (gp0 < gp1) {
        const int batch = (int)(gp0 >> 10);
        const int pbase = (int)(gp0 & 1023u);
        const int cnt   = min((int)(gp1 - gp0), 1024 - pbase);
        const float* __restrict__ xb = inputs + (size_t)batch * LSEQ * 3;

        if (batch != prev_batch) {
            __syncthreads();     // protect prior segment's tile readers
            float wk[9], wv[9], bk[3], bv[3];
            #pragma unroll
            for (int i = 0; i < 9; i++) { wk[i] = wi[9 + i]; wv[i] = wi[18 + i]; }
            #pragma unroll
            for (int i = 0; i < 3; i++) { bk[i] = bi[3 + i]; bv[i] = bi[6 + i]; }
            #pragma unroll
            for (int r = t; r < LSEQ; r += TPB) {
                float x0 = xb[3 * r + 0];
                float x1 = xb[3 * r + 1] * inv0;
                float x2 = xb[3 * r + 2] * inv1;
                float k0 = bk[0] + wk[0] * x0 + wk[1] * x1 + wk[2] * x2;
                float k1 = bk[1] + wk[3] * x0 + wk[4] * x1 + wk[5] * x2;
                float k2 = bk[2] + wk[6] * x0 + wk[7] * x1 + wk[8] * x2;
                float v0 = bv[0] + wv[0] * x0 + wv[1] * x1 + wv[2] * x2;
                float v1 = bv[1] + wv[3] * x0 + wv[4] * x1 + wv[5] * x2;
                float v2 = bv[2] + wv[6] * x0 + wv[7] * x1 + wv[8] * x2;
                kv[2 * r + 0] = make_float4(k0, k1, k2, 0.0f);
                kv[2 * r + 1] = make_float4(v0, v1, v2, 1.0f);
            }
            __syncthreads();
            prev_batch = batch;
        }

        if (u < cnt) {
            const int p = pbase + u;
            const int i = hi_half ? (LSEQ - 1 - p) : p;

            // q projection, pre-scaled for ex2
            float q0, q1, q2;
            {
                float x0 = xb[3 * i + 0];
                float x1 = xb[3 * i + 1] * inv0;
                float x2 = xb[3 * i + 2] * inv1;
                q0 = (bi[0] + wi[0] * x0 + wi[1] * x1 + wi[2] * x2) * QSCALE;
                q1 = (bi[1] + wi[3] * x0 + wi[4] * x1 + wi[5] * x2) * QSCALE;
                q2 = (bi[2] + wi[6] * x0 + wi[7] * x1 + wi[8] * x2) * QSCALE;
            }

            unsigned long long acc01 = 0ull, acc2d = 0ull;  // {a0,a1}, {a2,den}
            #pragma unroll 4
            for (int j = 0; j <= i; j++) {
                float4 K = kv[2 * j];        // broadcast LDS.128
                float4 V = kv[2 * j + 1];    // broadcast LDS.128 (pairs {v0,v1},{v2,1})
                float sc = fmaf(K.z, q2, fmaf(K.y, q1, K.x * q0));
                float w  = ex2(sc);
                unsigned long long wp, vp01, vp2d;
                PACK2(wp, w, w);
                PACK2(vp01, V.x, V.y);       // aligned halves of V's quad
                PACK2(vp2d, V.z, V.w);
                FMA2(acc01, wp, vp01, acc01);
                FMA2(acc2d, wp, vp2d, acc2d);
            }

            float a0, a1, a2, den;
            UNPACK2(a0, a1, acc01);
            UNPACK2(a2, den, acc2d);
            const float r  = 1.0f / den;
            const float c0 = a0 * r, c1 = a1 * r, c2 = a2 * r;

            float s1 = bo1 + wo10 * c0 + wo11 * c1 + wo12 * c2;
            float s2 = bo2 + wo20 * c0 + wo21 * c1 + wo22 * c2;

            float o[8];
            {
                float d1 = (G10 + G11 * s1 + G12 * s2 + G1B) * M1;
                float d2 = (G20 + G21 * s1 + G22 * s2 + G2B) * M2;
                s1 += DTC * d1; s2 += DTC * d2;
                o[0] = s1 * scl0; o[1] = s2 * scl1;
            }
            {
                float d1 = (G10 + G11 * s1 + G12 * s2 + G1B) * M1;
                float d2 = (G20 + G21 * s1 + G22 * s2 + G2B) * M2;
                s1 += DTC * d1; s2 += DTC * d2;
                o[2] = s1 * scl0; o[3] = s2 * scl1;
            }
            {
                float d1 = (G10 + G11 * s1 + G12 * s2 + G1B) * M1;
                float d2 = (G20 + G21 * s1 + G22 * s2 + G2B) * M2;
                s1 += DTC * d1; s2 += DTC * d2;
                o[4] = s1 * scl0; o[5] = s2 * scl1;
            }
            {
                float v1 = (F10 + F11 * s1 + F12 * s2 + F1B) * M1;
                float v2 = (F20 + F21 * s1 + F22 * s2 + F2B) * M2;
                o[6] = (s1 + v1 * DTC) * scl0;
                o[7] = (s2 + v2 * DTC) * scl1;
            }

            float4* op = reinterpret_cast<float4*>(out) + ((size_t)(batch * LSEQ + i)) * 2;
            op[0] = make_float4(o[0], o[1], o[2], o[3]);
            op[1] = make_float4(o[4], o[5], o[6], o[7]);
        }

        gp0 += (unsigned)cnt;
    }
}

extern "C" void kernel_launch(void* const* d_in, const int* in_sizes, int n_in,
                              void* d_out, int out_size)
{
    const float* inputs = (const float*)d_in[1];
    const float* wi     = (const float*)d_in[2];
    const float* bi     = (const float*)d_in[3];
    const float* wo     = (const float*)d_in[4];
    const float* bo     = (const float*)d_in[5];
    const float* f1w    = (const float*)d_in[6];
    const float* f1b    = (const float*)d_in[7];
    const float* f2w    = (const float*)d_in[8];
    const float* f2b    = (const float*)d_in[9];
    const float* g1w    = (const float*)d_in[10];
    const float* g1b    = (const float*)d_in[11];
    const float* g2w    = (const float*)d_in[12];
    const float* g2b    = (const float*)d_in[13];
    const float* m1s    = (const float*)d_in[14];
    const float* m2s    = (const float*)d_in[15];
    const float* sigma  = (const float*)d_in[16];
    float* out = (float*)d_out;

    const int smem = 2 * LSEQ * (int)sizeof(float4);   // 64 KB
    cudaFuncSetAttribute(ac_kernel, cudaFuncAttributeMaxDynamicSharedMemorySize, smem);

    ac_kernel<<<NBLOCKS, TPB, smem>>>(inputs, wi, bi, wo, bo,
                                      f1w, f1b, f2w, f2b,
                                      g1w, g1b, g2w, g2b,
                                      m1s, m2s, sigma, out);
}